// round 1
// baseline (speedup 1.0000x reference)
#include <cuda_runtime.h>
#include <cuda_bf16.h>

typedef unsigned long long u64;

// Problem constants
#define Bc   64
#define DINc 150528
#define Dc   512
#define Cc   100
#define Mc   64
#define NFc  256
#define KC   1024
#define NCH  147          // 147 * 1024 = 150528
#define DT   128

// Scratch (static device memory — no allocation)
__device__ float g_partial[NCH * Bc * Dc];   // split-K partials: [chunk][b][d]
__device__ float g_f[Bc * Dc];               // normalized features
__device__ float g_kwp[2 * Cc * NFc];        // kw partial per m-half

// ---------------------------------------------------------------------------
// packed f32x2 helpers (sm_100+ PTX)
// ---------------------------------------------------------------------------
__device__ __forceinline__ u64 splat2(float x) {
    u64 r;
    asm("mov.b64 %0, {%1, %1};" : "=l"(r) : "f"(x));
    return r;
}
__device__ __forceinline__ void fma2(u64& d, u64 a, u64 b) {
    asm("fma.rn.f32x2 %0, %1, %2, %0;" : "+l"(d) : "l"(a), "l"(b));
}
__device__ __forceinline__ float2 unpack2(u64 v) {
    float2 r;
    asm("mov.b64 {%0, %1}, %2;" : "=f"(r.x), "=f"(r.y) : "l"(v));
    return r;
}

// ---------------------------------------------------------------------------
// K1: split-K GEMM  f_raw = image @ W_enc  (64 x 150528) * (150528 x 512)
// grid (4 d-tiles, 147 k-chunks), 256 threads.
// Each block: 64 x 128 output tile over a 1024-deep K chunk -> g_partial.
// Inner loop uses fma.rn.f32x2 (2 FMAs/inst) to double fp32 throughput.
// ---------------------------------------------------------------------------
__global__ void __launch_bounds__(256)
gemm_kernel(const float* __restrict__ A, const float* __restrict__ W) {
    __shared__ float As[32 * 68];    // [kk][b] (padded stride 68)
    __shared__ float Bs[32 * 128];   // [kk][d]

    const int t  = threadIdx.x;
    const int tx = t & 31;           // column group (4 cols)
    const int ty = t >> 5;           // row group (8 rows)
    const int dt0 = blockIdx.x * DT;
    const size_t kb = (size_t)blockIdx.y * KC;

    u64 acc[4][4];                   // [row-pair][col], each holds rows (2i, 2i+1)
#pragma unroll
    for (int i = 0; i < 4; i++)
#pragma unroll
        for (int j = 0; j < 4; j++) acc[i][j] = 0ull;

    for (int k0 = 0; k0 < KC; k0 += 32) {
        // Load A tile: 64 rows x 32 k  (512 float4, 2 per thread), transpose to As[kk][b]
#pragma unroll
        for (int v = 0; v < 2; v++) {
            int ss = t * 2 + v;
            int b  = ss >> 3;
            int f4 = ss & 7;
            float4 av = *(const float4*)&A[(size_t)b * DINc + kb + k0 + f4 * 4];
            As[(f4 * 4 + 0) * 68 + b] = av.x;
            As[(f4 * 4 + 1) * 68 + b] = av.y;
            As[(f4 * 4 + 2) * 68 + b] = av.z;
            As[(f4 * 4 + 3) * 68 + b] = av.w;
        }
        // Load B tile: 32 k x 128 d (1024 float4, 4 per thread), coalesced
#pragma unroll
        for (int i = 0; i < 4; i++) {
            int ss = t + i * 256;
            int kk = ss >> 5;
            int dv = ss & 31;
            *(float4*)&Bs[kk * 128 + dv * 4] =
                *(const float4*)&W[(kb + k0 + kk) * (size_t)Dc + dt0 + dv * 4];
        }
        __syncthreads();

#pragma unroll
        for (int kk = 0; kk < 32; kk++) {
            u64 pa[4];
#pragma unroll
            for (int i = 0; i < 4; i++)
                pa[i] = *(const u64*)&As[kk * 68 + ty * 8 + 2 * i];  // row pair (packed)
            float4 b4 = *(const float4*)&Bs[kk * 128 + tx * 4];
            u64 pb0 = splat2(b4.x), pb1 = splat2(b4.y);
            u64 pb2 = splat2(b4.z), pb3 = splat2(b4.w);
#pragma unroll
            for (int i = 0; i < 4; i++) {
                fma2(acc[i][0], pa[i], pb0);
                fma2(acc[i][1], pa[i], pb1);
                fma2(acc[i][2], pa[i], pb2);
                fma2(acc[i][3], pa[i], pb3);
            }
        }
        __syncthreads();
    }

    // Store partials, coalesced float4 per row
#pragma unroll
    for (int i = 0; i < 4; i++) {
        float2 c0 = unpack2(acc[i][0]);
        float2 c1 = unpack2(acc[i][1]);
        float2 c2 = unpack2(acc[i][2]);
        float2 c3 = unpack2(acc[i][3]);
        int row = ty * 8 + i * 2;
        size_t base = ((size_t)(blockIdx.y * 64 + row)) * Dc + dt0 + tx * 4;
        float4 v0 = make_float4(c0.x, c1.x, c2.x, c3.x);
        float4 v1 = make_float4(c0.y, c1.y, c2.y, c3.y);
        *(float4*)&g_partial[base]       = v0;
        *(float4*)&g_partial[base + Dc]  = v1;
    }
}

// ---------------------------------------------------------------------------
// K2: reduce split-K partials + L2-normalize rows.  grid(64), 256 threads.
// ---------------------------------------------------------------------------
__global__ void __launch_bounds__(256)
reduce_norm_kernel() {
    const int b = blockIdx.x;
    const int t = threadIdx.x;
    float v0 = 0.f, v1 = 0.f;
#pragma unroll 7
    for (int ch = 0; ch < NCH; ch++) {
        const float* p = &g_partial[((size_t)ch * Bc + b) * Dc];
        v0 += p[t];
        v1 += p[t + 256];
    }
    __shared__ float red[256];
    red[t] = v0 * v0 + v1 * v1;
    __syncthreads();
    for (int s = 128; s > 0; s >>= 1) {
        if (t < s) red[t] += red[t + s];
        __syncthreads();
    }
    __shared__ float inv;
    if (t == 0) inv = rsqrtf(red[0]);
    __syncthreads();
    g_f[b * Dc + t]       = v0 * inv;
    g_f[b * Dc + t + 256] = v1 * inv;
}

// ---------------------------------------------------------------------------
// K3: per-class key softmax -> w[c,m] -> kw partial.
// grid (100 classes, 2 m-halves), 256 threads. Static smem < 34 KB.
// kw[c,f] = sum_m keys_sel[c,m,f] * w[c,m];  stored per half in g_kwp.
// ---------------------------------------------------------------------------
__global__ void __launch_bounds__(256)
wkw_kernel(const float* __restrict__ text, const float* __restrict__ keys,
           const int* __restrict__ indices, const float* __restrict__ gamma_p) {
    __shared__ float keys_s[32 * 256];   // gathered keys half-tile [ml][f]
    __shared__ float ts[256];            // gathered text row
    __shared__ float wsh[32];
    __shared__ int idx[256];

    const int c  = blockIdx.x;
    const int mh = blockIdx.y;           // m half: 0 or 1
    const int t  = threadIdx.x;

    idx[t] = indices[c * NFc + t];
    __syncthreads();

    // Gather keys_sel half: 32 m-rows x 256 f
    for (int s = t; s < 32 * 256; s += 256) {
        int ml = s >> 8;
        int f  = s & 255;
        keys_s[s] = keys[((size_t)(c * Mc + mh * 32 + ml)) * Dc + idx[f]];
    }
    __syncthreads();

    const int ml = t >> 3;               // 0..31
    const int p  = t & 7;                // 8 lanes per m, 32 f each
    float denom = 0.f, numer = 0.f;

    for (int j = 0; j < Cc; j++) {
        ts[t] = text[j * Dc + idx[t]];
        __syncthreads();
        float s = 0.f;
#pragma unroll 8
        for (int q = 0; q < 32; q++) {
            int fq = p * 32 + ((q + t) & 31);   // lane-rotated -> conflict-free
            s += keys_s[ml * 256 + fq] * ts[fq];
        }
        s += __shfl_xor_sync(0xffffffffu, s, 1);
        s += __shfl_xor_sync(0xffffffffu, s, 2);
        s += __shfl_xor_sync(0xffffffffu, s, 4);
        float e = expf(s);
        denom += e;
        if (j == c) numer = e;
        __syncthreads();
    }

    if (p == 0) {
        float pcc = numer / denom;
        float KL  = log2f((1.f + 1e-6f) / (pcc + 1e-6f));
        wsh[ml]   = expf(KL * gamma_p[0]);
    }
    __syncthreads();

    // kw partial over this m half
    float acc = 0.f;
#pragma unroll 8
    for (int mm = 0; mm < 32; mm++)
        acc += keys_s[mm * 256 + t] * wsh[mm];
    g_kwp[(size_t)mh * Cc * NFc + c * NFc + t] = acc;
}

// ---------------------------------------------------------------------------
// K4: final fused epilogue. grid(100 classes), 256 threads.
// out[b,c] = alpha*exp(beta*cache-beta) + exp(ls)*(f[b]·text[c])
// cache = (1/M) * sum_f f[b, idx[c,f]] * kw[c,f]
// ---------------------------------------------------------------------------
__global__ void __launch_bounds__(256)
final_kernel(const float* __restrict__ text, const int* __restrict__ indices,
             const float* __restrict__ ls_p, const float* __restrict__ alpha_p,
             const float* __restrict__ beta_p, float* __restrict__ out) {
    __shared__ float tc[512];
    __shared__ float kws[256];
    __shared__ int idx[256];

    const int c = blockIdx.x;
    const int t = threadIdx.x;

    tc[t]       = text[c * Dc + t];
    tc[t + 256] = text[c * Dc + 256 + t];
    idx[t]      = indices[c * NFc + t];
    kws[t]      = g_kwp[c * NFc + t] + g_kwp[Cc * NFc + c * NFc + t];
    __syncthreads();

    const int b = t >> 2;                // 0..63
    const int p = t & 3;                 // 4 lanes per b
    const float* fb = &g_f[b * Dc];

    float clip = 0.f;
#pragma unroll 8
    for (int q = 0; q < 32; q++) {
        float4 fv = *(const float4*)&fb[p * 128 + q * 4];
        float4 tv = *(const float4*)&tc[p * 128 + q * 4];
        clip += fv.x * tv.x + fv.y * tv.y + fv.z * tv.z + fv.w * tv.w;
    }
    float cache = 0.f;
#pragma unroll 8
    for (int q = 0; q < 64; q++) {
        int ff = p * 64 + q;
        cache += fb[idx[ff]] * kws[ff];
    }
    clip  += __shfl_xor_sync(0xffffffffu, clip, 1);
    clip  += __shfl_xor_sync(0xffffffffu, clip, 2);
    cache += __shfl_xor_sync(0xffffffffu, cache, 1);
    cache += __shfl_xor_sync(0xffffffffu, cache, 2);

    if (p == 0) {
        float cl = cache * (1.f / (float)Mc);
        float cache_logit = expf(beta_p[0] * cl - beta_p[0]);
        out[b * Cc + c] = alpha_p[0] * cache_logit + expf(ls_p[0]) * clip;
    }
}

// ---------------------------------------------------------------------------
// Launch
// ---------------------------------------------------------------------------
extern "C" void kernel_launch(void* const* d_in, const int* in_sizes, int n_in,
                              void* d_out, int out_size) {
    const float* image   = (const float*)d_in[0];
    const float* W_enc   = (const float*)d_in[1];
    const float* text    = (const float*)d_in[2];
    const float* keys    = (const float*)d_in[3];
    const float* ls      = (const float*)d_in[4];
    const int*   indices = (const int*)d_in[5];
    const float* alpha   = (const float*)d_in[6];
    const float* beta    = (const float*)d_in[7];
    const float* gamma   = (const float*)d_in[8];
    float* out = (float*)d_out;

    gemm_kernel<<<dim3(4, NCH), 256>>>(image, W_enc);
    reduce_norm_kernel<<<Bc, 256>>>();
    wkw_kernel<<<dim3(Cc, 2), 256>>>(text, keys, indices, gamma);
    final_kernel<<<Cc, 256>>>(text, indices, ls, alpha, beta, out);
}